// round 11
// baseline (speedup 1.0000x reference)
#include <cuda_runtime.h>

// URPE: out[b,h,i,j] = attention_probs[b,h,i,j] * toe[h,i,j]
// toe[h,i,j] = w[h, L + j - i] if j >= i else w[h, i - j].
//
// B=2, H=16, L=2048. HBM-bound streaming multiply; traffic at its 1.074 GB
// floor. R9 showed per-thread load batching (not occupancy) is the binding
// lever: hoisting weight LDGs raised DRAM 84.9->85.7%.
// R10: double down — ILP=8, ALL 40 loads per thread front-batched
// (8 stream LDG.128.CS + 32 weight LDGs), __launch_bounds__(256, 2).

static constexpr int LDIM = 2048;
static constexpr int HDIM = 16;
static constexpr int BDIM = 2;
static constexpr int VEC_PER_ROW = LDIM / 4;            // 512 float4 per row
static constexpr long long NVEC =
    (long long)BDIM * HDIM * LDIM * LDIM / 4;           // 33,554,432
static constexpr int THREADS = 256;
static constexpr int ILP = 8;                           // float4s per thread

__global__ __launch_bounds__(THREADS, 2)
void urpe_mul_kernel(const float4* __restrict__ probs,
                     const float*  __restrict__ w,
                     float4*       __restrict__ out) {
    const unsigned int base = blockIdx.x * (THREADS * ILP) + threadIdx.x;

    // Phase 1: front-batch all 8 independent stream loads (LDG.128.CS).
    float4 v[ILP];
#pragma unroll
    for (int k = 0; k < ILP; k++)
        v[k] = __ldcs(&probs[base + k * THREADS]);

    // Phase 2: front-batch all 32 weight gathers (addresses = pure index
    // math, independent of stream loads; register budget lets ptxas keep
    // every load above the first FMUL).
    float tw[ILP][4];
#pragma unroll
    for (int k = 0; k < ILP; k++) {
        const unsigned int vid = base + k * THREADS;
        const unsigned int j0 = (vid & (VEC_PER_ROW - 1)) << 2;
        const unsigned int i  = (vid >> 9)  & (LDIM - 1);
        const unsigned int h  = (vid >> 20) & (HDIM - 1);
        const float* __restrict__ wh = w + h * (2 * LDIM);

        const int d = (int)j0 - (int)i;
        const int d0 = d,     o0 = (d0 >= 0) ? (LDIM + d0) : -d0;
        const int d1 = d + 1, o1 = (d1 >= 0) ? (LDIM + d1) : -d1;
        const int d2 = d + 2, o2 = (d2 >= 0) ? (LDIM + d2) : -d2;
        const int d3 = d + 3, o3 = (d3 >= 0) ? (LDIM + d3) : -d3;

        tw[k][0] = __ldg(wh + o0);
        tw[k][1] = __ldg(wh + o1);
        tw[k][2] = __ldg(wh + o2);
        tw[k][3] = __ldg(wh + o3);
    }

    // Phase 3: multiply + streaming stores.
#pragma unroll
    for (int k = 0; k < ILP; k++) {
        v[k].x *= tw[k][0];
        v[k].y *= tw[k][1];
        v[k].z *= tw[k][2];
        v[k].w *= tw[k][3];
        __stcs(&out[base + k * THREADS], v[k]);
    }
}

extern "C" void kernel_launch(void* const* d_in, const int* in_sizes, int n_in,
                              void* d_out, int out_size) {
    const float4* probs = (const float4*)d_in[0];   // attention_probs [B,H,L,L] f32
    const float*  w     = (const float*)d_in[1];    // urpe_weight_    [H,2L]   f32
    float4*       out   = (float4*)d_out;

    const int blocks = (int)(NVEC / (THREADS * ILP));  // 16384, exact
    urpe_mul_kernel<<<blocks, THREADS>>>(probs, w, out);
}

// round 12
// speedup vs baseline: 1.0012x; 1.0012x over previous
#include <cuda_runtime.h>

// URPE: out[b,h,i,j] = attention_probs[b,h,i,j] * toe[h,i,j]
// toe[h,i,j] = w[h, L + j - i] if j >= i else w[h, i - j].
//
// B=2, H=16, L=2048. HBM-bound streaming multiply; traffic at its 1.074 GB
// floor. Occupancy-vs-MLP curve: occ 84%/MLP20 -> 84.9% DRAM (R6),
// occ 50%/MLP20 -> 85.7% (R9, best), occ 31%/MLP40 -> 84.6% (R10, overshoot).
// R11: stream depth 8 (front-batched LDG.128.CS) + weights hoisted in TWO
// halves of 16 — R10's stream MLP at near-R9 register pressure.

static constexpr int LDIM = 2048;
static constexpr int HDIM = 16;
static constexpr int BDIM = 2;
static constexpr int VEC_PER_ROW = LDIM / 4;            // 512 float4 per row
static constexpr long long NVEC =
    (long long)BDIM * HDIM * LDIM * LDIM / 4;           // 33,554,432
static constexpr int THREADS = 256;
static constexpr int ILP = 8;                           // float4s per thread

__device__ __forceinline__ void gather_w(float tw[4], unsigned int vid,
                                         const float* __restrict__ w) {
    const unsigned int j0 = (vid & (VEC_PER_ROW - 1)) << 2;
    const unsigned int i  = (vid >> 9)  & (LDIM - 1);
    const unsigned int h  = (vid >> 20) & (HDIM - 1);
    const float* __restrict__ wh = w + h * (2 * LDIM);

    const int d = (int)j0 - (int)i;
    const int d0 = d,     o0 = (d0 >= 0) ? (LDIM + d0) : -d0;
    const int d1 = d + 1, o1 = (d1 >= 0) ? (LDIM + d1) : -d1;
    const int d2 = d + 2, o2 = (d2 >= 0) ? (LDIM + d2) : -d2;
    const int d3 = d + 3, o3 = (d3 >= 0) ? (LDIM + d3) : -d3;

    tw[0] = __ldg(wh + o0);
    tw[1] = __ldg(wh + o1);
    tw[2] = __ldg(wh + o2);
    tw[3] = __ldg(wh + o3);
}

__global__ __launch_bounds__(THREADS, 3)
void urpe_mul_kernel(const float4* __restrict__ probs,
                     const float*  __restrict__ w,
                     float4*       __restrict__ out) {
    const unsigned int base = blockIdx.x * (THREADS * ILP) + threadIdx.x;

    // Phase 1: front-batch all 8 independent stream loads (LDG.128.CS).
    float4 v[ILP];
#pragma unroll
    for (int k = 0; k < ILP; k++)
        v[k] = __ldcs(&probs[base + k * THREADS]);

    // Phase 2a: hoist weight gathers for the first half (16 loads in flight).
    float twa[4][4];
#pragma unroll
    for (int k = 0; k < 4; k++)
        gather_w(twa[k], base + k * THREADS, w);

    // Phase 2b: retire first half (mul + streaming store)...
#pragma unroll
    for (int k = 0; k < 4; k++) {
        v[k].x *= twa[k][0];
        v[k].y *= twa[k][1];
        v[k].z *= twa[k][2];
        v[k].w *= twa[k][3];
        __stcs(&out[base + k * THREADS], v[k]);
    }

    // Phase 3a: hoist weight gathers for the second half (reuses twa regs).
#pragma unroll
    for (int k = 0; k < 4; k++)
        gather_w(twa[k], base + (k + 4) * THREADS, w);

    // Phase 3b: retire second half.
#pragma unroll
    for (int k = 0; k < 4; k++) {
        v[k + 4].x *= twa[k][0];
        v[k + 4].y *= twa[k][1];
        v[k + 4].z *= twa[k][2];
        v[k + 4].w *= twa[k][3];
        __stcs(&out[base + (k + 4) * THREADS], v[k + 4]);
    }
}

extern "C" void kernel_launch(void* const* d_in, const int* in_sizes, int n_in,
                              void* d_out, int out_size) {
    const float4* probs = (const float4*)d_in[0];   // attention_probs [B,H,L,L] f32
    const float*  w     = (const float*)d_in[1];    // urpe_weight_    [H,2L]   f32
    float4*       out   = (float4*)d_out;

    const int blocks = (int)(NVEC / (THREADS * ILP));  // 16384, exact
    urpe_mul_kernel<<<blocks, THREADS>>>(probs, w, out);
}